// round 5
// baseline (speedup 1.0000x reference)
#include <cuda_runtime.h>
#include <cstdint>
#include <math.h>

// Accurate libdevice log (what XLA emits for lax.log on f32). Used for the
// exact fallback path and the rare near-u=1 fix so argmax ordering is
// provably identical to the reference.
extern "C" __device__ float __nv_logf(float);

// Opaque 1 — loaded from global memory so ptxas cannot fold a*one+b back to
// IADD3. This pins threefry adds onto the FMA pipe (IMAD), balancing against
// the saturated ALU pipe (SHF/LOP3).
__device__ unsigned g_one = 1u;

// ---------------------------------------------------------------------------
// Compile-time Threefry-2x32 for deriving split keys.
// Partitionable (fold-like) split: key_i = threefry(parent, (0, i)), both lanes.
// ---------------------------------------------------------------------------
constexpr unsigned crotl(unsigned x, int r) { return (x << r) | (x >> (32 - r)); }
struct CKeys { unsigned a, b; };
constexpr CKeys ctf(unsigned k0, unsigned k1, unsigned x0, unsigned x1) {
    unsigned k2 = k0 ^ k1 ^ 0x1BD11BDAu;
    const int rotA[4] = {13, 15, 26, 6};
    const int rotB[4] = {17, 29, 16, 24};
    x0 += k0; x1 += k1;
    for (int i = 0; i < 4; i++) { x0 += x1; x1 = crotl(x1, rotA[i]); x1 ^= x0; }
    x0 += k1; x1 += k2 + 1u;
    for (int i = 0; i < 4; i++) { x0 += x1; x1 = crotl(x1, rotB[i]); x1 ^= x0; }
    x0 += k2; x1 += k0 + 2u;
    for (int i = 0; i < 4; i++) { x0 += x1; x1 = crotl(x1, rotA[i]); x1 ^= x0; }
    x0 += k0; x1 += k1 + 3u;
    for (int i = 0; i < 4; i++) { x0 += x1; x1 = crotl(x1, rotB[i]); x1 ^= x0; }
    x0 += k1; x1 += k2 + 4u;
    for (int i = 0; i < 4; i++) { x0 += x1; x1 = crotl(x1, rotA[i]); x1 ^= x0; }
    x0 += k2; x1 += k0 + 5u;
    return {x0, x1};
}
constexpr CKeys KCAT  = ctf(0u, 42u, 0u, 0u);   // k_cat
constexpr CKeys KBERN = ctf(0u, 42u, 0u, 1u);   // k_bern

// ---------------------------------------------------------------------------
// Device Threefry-2x32; partitionable 32-bit random_bits = lane0 ^ lane1,
// counter = (0, j). All adds routed through IMAD via the opaque 'one'.
// ---------------------------------------------------------------------------
__device__ __forceinline__ unsigned rotl(unsigned x, int r) {
    return __funnelshift_l(x, x, r);
}

__device__ __forceinline__ unsigned tf_bits32(unsigned one, unsigned k0,
                                              unsigned k1, unsigned x1) {
#define ADDI(a, b) ((a) * one + (b))
    unsigned k2 = k0 ^ k1 ^ 0x1BD11BDAu;
    unsigned x0 = k0;
    x1 = ADDI(x1, k1);
#define TFR(r) { x0 = ADDI(x0, x1); x1 = rotl(x1, r); x1 ^= x0; }
    TFR(13) TFR(15) TFR(26) TFR(6)
    x0 = ADDI(x0, k1); x1 = ADDI(x1, k2 + 1u);
    TFR(17) TFR(29) TFR(16) TFR(24)
    x0 = ADDI(x0, k2); x1 = ADDI(x1, k0 + 2u);
    TFR(13) TFR(15) TFR(26) TFR(6)
    x0 = ADDI(x0, k0); x1 = ADDI(x1, k1 + 3u);
    TFR(17) TFR(29) TFR(16) TFR(24)
    x0 = ADDI(x0, k1); x1 = ADDI(x1, k2 + 4u);
    TFR(13) TFR(15) TFR(26) TFR(6)
#undef TFR
    return ADDI(x0, k2) ^ ADDI(x1, k0 + 5u);
#undef ADDI
}

// JAX uniform [0,1): bitcast((bits>>9)|0x3f800000) - 1
__device__ __forceinline__ float u01f(unsigned bits) {
    return __uint_as_float((bits >> 9) | 0x3f800000u) - 1.0f;
}

#define TINY   1.17549435e-38f
#define T_MIN  0.001953125f     /* 2^-9: below this, MUFU abs-err on log(u) is */
                                /* relatively too large -> exact fix           */
#define GAPTHR 1e-3f            /* > 2.6x the max cheap-score error (~2e-4)    */

// ---------------------------------------------------------------------------
// One thread per 8x8 window.
// Cheap pass: __logf-based gumbel scores (error <= ~2e-4 after the t<2^-9
// exact fix), top-2 tracked. If top-2 gap < GAPTHR, redo the window with the
// bitwise-exact libdevice formula (P ~ 1e-3). Winner == reference winner.
// ---------------------------------------------------------------------------
__global__ __launch_bounds__(128)
void keypoint_sampler_kernel(const float* __restrict__ x, float* __restrict__ out) {
    const unsigned one = g_one;                          // opaque 1
    const unsigned w = blockIdx.x * 128u + threadIdx.x;  // 0 .. 524287

    const unsigned b  = w >> 16;
    const unsigned hc = (w >> 8) & 255u;
    const unsigned wc = w & 255u;

    const float* base = x + ((size_t)b << 22) + (size_t)(hc * 8u) * 2048u + wc * 8u;

    // Bernoulli bits early (independent ILP)
    const unsigned bbits = tf_bits32(one, KBERN.a, KBERN.b, w);

    float best = -3.4e38f, b2 = -3.4e38f;
    int   bi   = 0;
    float esum = 0.0f;

    const unsigned cbase = w * 64u;

#pragma unroll 1
    for (int r = 0; r < 8; r++) {
        const float4 p0 = *(const float4*)(base + (size_t)r * 2048u);
        const float4 p1 = *(const float4*)(base + (size_t)r * 2048u + 4u);
        float v[8] = {p0.x, p0.y, p0.z, p0.w, p1.x, p1.y, p1.z, p1.w};

        const unsigned c = cbase + (unsigned)r * 8u;
#pragma unroll
        for (int i = 0; i < 8; i++) {
            const unsigned gb = tf_bits32(one, KCAT.a, KCAT.b, c + (unsigned)i);
            const float u = fmaxf(u01f(gb), TINY);
            float t = -__logf(u);
            if (t < T_MIN) t = -__nv_logf(u);   // rare (P~2e-3/lane) exact fix
            const float s = v[i] - __logf(t);
            esum += __expf(v[i]);
            if (s > best) { b2 = best; best = s; bi = r * 8 + i; }
            else          { b2 = fmaxf(b2, s); }
        }
    }

    // Ambiguous top-2 (P ~ 1e-3): redo window with the bitwise-exact formula.
    if (best - b2 < GAPTHR) {
        best = -3.4e38f; bi = 0;
#pragma unroll 1
        for (int r = 0; r < 8; r++) {
#pragma unroll 1
            for (int i = 0; i < 8; i++) {
                const unsigned gb = tf_bits32(one, KCAT.a, KCAT.b,
                                              cbase + (unsigned)(r * 8 + i));
                const float u = fmaxf(u01f(gb), TINY);
                const float t = -__nv_logf(u);
                const float s = __ldg(base + (size_t)r * 2048u + (unsigned)i)
                                - __nv_logf(t);
                if (s > best) { best = s; bi = r * 8 + i; }
            }
        }
    }

    // Selected grid value via one cached load
    const float sel = __ldg(base + (size_t)(bi >> 3) * 2048u + (unsigned)(bi & 7));

    const float u = u01f(bbits);

    // Fast f32 sigmoid decides unless u is within 2e-3 of it; ambiguous
    // threads (~0.1%) use the correctly-rounded double path. Identical
    // decision to always-double.
    const float e    = __expf(-fabsf(sel));
    const float rr   = __fdividef(1.0f, 1.0f + e);
    const float sigf = (sel >= 0.0f) ? rr : 1.0f - rr;
    const float du   = u - sigf;
    bool acc;
    if (fabsf(du) > 2e-3f) {
        acc = du < 0.0f;
    } else {
        const double sig = 1.0 / (1.0 + exp(-(double)sel));
        acc = u < (float)sig;
    }

    const float lse     = log1pf(e);
    const float bern_lp = (acc ? fminf(sel, 0.0f) : fminf(-sel, 0.0f)) - lse;
    const float cat_lp  = sel - __logf(esum);   // abs err ~2e-6, tol 1e-3

    const int ddi = bi >> 3, ddj = bi & 7;

    // tuple layout: kp_xy [2*524288] | log_probs [524288] | mask [524288]
    ((float2*)out)[w]  = make_float2((float)(wc * 8u + (unsigned)ddj),   // x=col
                                     (float)(hc * 8u + (unsigned)ddi)); // y=row
    out[1048576u + w]  = cat_lp + bern_lp;
    out[1572864u + w]  = acc ? 1.0f : 0.0f;
}

extern "C" void kernel_launch(void* const* d_in, const int* in_sizes, int n_in,
                              void* d_out, int out_size) {
    const float* x = (const float*)d_in[0];
    float* out = (float*)d_out;
    keypoint_sampler_kernel<<<4096, 128>>>(x, out);
}